// round 3
// baseline (speedup 1.0000x reference)
#include <cuda_runtime.h>
#include <cstdint>
#include <cstddef>

#define NN      100000
#define EE      800000
#define ETOT    (EE + NN)          // 900000 with self loops
#define IN_DIM  32
#define HID     128
#define HEADS   4
#define CH      32
#define LAYERS  3
#define OUT_DIM 5

// ---------------- scratch (device globals; allocation-free) ----------------
__device__ int g_is64;
__device__ __align__(16) int      g_src[ETOT];
__device__ __align__(16) int      g_dst[ETOT];
__device__ __align__(16) float    g_ea[ETOT];
__device__ __align__(16) float    g_deg[NN];
__device__ __align__(16) float    g_lsum[NN];
__device__ __align__(16) float    g_h[NN * HID];
__device__ __align__(16) float    g_xh[NN * HID];
__device__ __align__(16) float    g_gg[NN * HID];
__device__ __align__(16) float    g_als[NN * HEADS];
__device__ __align__(16) float    g_ald[NN * HEADS];
__device__ __align__(16) unsigned g_m[NN * HEADS];     // max keys, then decoded floats
__device__ __align__(16) float    g_den[NN * HEADS];
__device__ __align__(16) float    g_logit[(size_t)ETOT * HEADS];  // logits, then exp()
__device__ double g_red[2];
__device__ __align__(16) float    g_coef[HEADS];

// ---------------- helpers ----------------
__device__ __forceinline__ unsigned fkey(float f) {
    unsigned b = __float_as_uint(f);
    return (b & 0x80000000u) ? ~b : (b | 0x80000000u);   // monotone float->uint
}
__device__ __forceinline__ float funkey(unsigned k) {
    unsigned b = (k & 0x80000000u) ? (k ^ 0x80000000u) : ~k;
    return __uint_as_float(b);
}

// ---------------- setup kernels ----------------
// edge_index declared int64 in the reference, but JAX without x64 silently
// stores int32. Detect on-device: int64 layout has all-zero high words.
__global__ void detect_kernel(const int* __restrict__ ei) {
    __shared__ int cnt;
    if (threadIdx.x == 0) cnt = 0;
    __syncthreads();
    int c = 0;
    for (int i = threadIdx.x; i < 1024; i += blockDim.x)
        if (ei[2 * i + 1] != 0) c++;
    atomicAdd(&cnt, c);
    __syncthreads();
    if (threadIdx.x == 0) g_is64 = (cnt == 0) ? 1 : 0;
}

__global__ void setup_zero_kernel() {
    int i = blockIdx.x * blockDim.x + threadIdx.x;
    if (i < NN) { g_deg[i] = 0.f; g_lsum[i] = 0.f; }
}

__global__ void convert_kernel(const int* __restrict__ ei) {
    int e = blockIdx.x * blockDim.x + threadIdx.x;
    if (e >= EE) return;
    int s, d;
    if (g_is64) { s = ei[2 * e]; d = ei[2 * EE + 2 * e]; }
    else        { s = ei[e];     d = ei[EE + e]; }
    g_src[e] = s;
    g_dst[e] = d;
}

__global__ void deg_kernel(const float* __restrict__ ea) {
    int e = blockIdx.x * blockDim.x + threadIdx.x;
    if (e >= EE) return;
    float a = ea[e];
    g_ea[e] = a;
    int d = g_dst[e];
    atomicAdd(&g_deg[d], 1.f);
    atomicAdd(&g_lsum[d], a);
}

__global__ void selfloop_kernel() {
    int i = blockIdx.x * blockDim.x + threadIdx.x;
    if (i >= NN) return;
    g_src[EE + i] = i;
    g_dst[EE + i] = i;
    g_ea[EE + i]  = g_lsum[i] / fmaxf(g_deg[i], 1.f);   // fill_value='mean'
}

// h = x @ Win + b_in   (one block = one node, 128 threads)
__global__ void input_proj_kernel(const float* __restrict__ x,
                                  const float* __restrict__ Win,
                                  const float* __restrict__ b_in) {
    int n = blockIdx.x;
    int c = threadIdx.x;
    __shared__ float xs[IN_DIM];
    if (c < IN_DIM) xs[c] = x[n * IN_DIM + c];
    __syncthreads();
    float acc = b_in[c];
#pragma unroll
    for (int k = 0; k < IN_DIM; k++) acc += xs[k] * Win[k * HID + c];
    g_h[n * HID + c] = acc;
}

// ---------------- per-layer kernels ----------------
__global__ void layer_zero_kernel() {
    int i = blockIdx.x * blockDim.x + threadIdx.x;
    if (i < NN * HID) g_gg[i] = 0.f;
    if (i < NN * HEADS) { g_m[i] = 0u; g_den[i] = 0.f; }
    if (i < 2) g_red[i] = 0.0;
}

// xh = h @ W  (128x128 weights). Tile 128 rows x 128 cols, 256 threads, 8x8/thread.
__global__ __launch_bounds__(256, 2) void gemm128_kernel(const float* __restrict__ W) {
    __shared__ float Ws[32][128];
    __shared__ float As[32][132];   // transposed A chunk; 132 pad keeps 16B align + spreads banks
    int t  = threadIdx.x;
    int tx = t & 15;
    int ty = t >> 4;
    int row0 = blockIdx.x * 128;
    float acc[8][8];
#pragma unroll
    for (int i = 0; i < 8; i++)
#pragma unroll
        for (int j = 0; j < 8; j++) acc[i][j] = 0.f;

    for (int k0 = 0; k0 < 128; k0 += 32) {
#pragma unroll
        for (int j = 0; j < 4; j++) {
            int idx = t + 256 * j;          // 0..1023 float4 slots
            int kk  = idx >> 5;
            int cc  = (idx & 31) << 2;
            *(float4*)&Ws[kk][cc] = *(const float4*)&W[(k0 + kk) * 128 + cc];
        }
#pragma unroll
        for (int j = 0; j < 4; j++) {
            int idx = t + 256 * j;
            int rr  = idx >> 3;
            int kk  = (idx & 7) << 2;
            int grow = row0 + rr;
            float4 a4 = make_float4(0.f, 0.f, 0.f, 0.f);
            if (grow < NN) a4 = *(const float4*)&g_h[grow * HID + k0 + kk];
            As[kk + 0][rr] = a4.x;
            As[kk + 1][rr] = a4.y;
            As[kk + 2][rr] = a4.z;
            As[kk + 3][rr] = a4.w;
        }
        __syncthreads();
#pragma unroll
        for (int k = 0; k < 32; k++) {
            float4 w0 = *(float4*)&Ws[k][4 * tx];
            float4 w1 = *(float4*)&Ws[k][64 + 4 * tx];
            float4 a0 = *(float4*)&As[k][8 * ty];
            float4 a1 = *(float4*)&As[k][8 * ty + 4];
            float wv[8] = {w0.x, w0.y, w0.z, w0.w, w1.x, w1.y, w1.z, w1.w};
            float av[8] = {a0.x, a0.y, a0.z, a0.w, a1.x, a1.y, a1.z, a1.w};
#pragma unroll
            for (int i = 0; i < 8; i++)
#pragma unroll
                for (int j = 0; j < 8; j++)
                    acc[i][j] += av[i] * wv[j];
        }
        __syncthreads();
    }
#pragma unroll
    for (int i = 0; i < 8; i++) {
        int r = row0 + 8 * ty + i;
        if (r < NN) {
            *(float4*)&g_xh[r * HID + 4 * tx]      = make_float4(acc[i][0], acc[i][1], acc[i][2], acc[i][3]);
            *(float4*)&g_xh[r * HID + 64 + 4 * tx] = make_float4(acc[i][4], acc[i][5], acc[i][6], acc[i][7]);
        }
    }
}

// al_s[n,h] = xh[n,h,:].a_src[h,:]  (warp per node)
__global__ void al_kernel(const float* __restrict__ asrc, const float* __restrict__ adst) {
    int gw   = (blockIdx.x * blockDim.x + threadIdx.x) >> 5;
    int lane = threadIdx.x & 31;
    if (gw >= NN) return;
    float4 xv = *(const float4*)&g_xh[gw * HID + 4 * lane];
    int h   = lane >> 3;
    int off = (lane & 7) << 2;
    float4 as = *(const float4*)&asrc[h * CH + off];
    float4 ad = *(const float4*)&adst[h * CH + off];
    float s = xv.x * as.x + xv.y * as.y + xv.z * as.z + xv.w * as.w;
    float d = xv.x * ad.x + xv.y * ad.y + xv.z * ad.z + xv.w * ad.w;
#pragma unroll
    for (int o = 4; o > 0; o >>= 1) {
        s += __shfl_down_sync(0xffffffffu, s, o, 8);
        d += __shfl_down_sync(0xffffffffu, d, o, 8);
    }
    if ((lane & 7) == 0) { g_als[gw * 4 + h] = s; g_ald[gw * 4 + h] = d; }
}

// al_e[e,h] = ea[e] * (We[h,:] . a_edge[h,:])  -> 4 scalars per layer
__global__ void coef_kernel(const float* __restrict__ We, const float* __restrict__ ae) {
    int h = threadIdx.x;
    if (h < HEADS) {
        float s = 0.f;
        for (int c = 0; c < CH; c++) s += We[h * CH + c] * ae[h * CH + c];
        g_coef[h] = s;
    }
}

// logits + segment max (atomicMax on monotone uint keys)
__global__ void logits_kernel() {
    int e = blockIdx.x * blockDim.x + threadIdx.x;
    if (e >= ETOT) return;
    int s = g_src[e], d = g_dst[e];
    float4 as = *(const float4*)&g_als[s * 4];
    float4 ad = *(const float4*)&g_ald[d * 4];
    float  ea = g_ea[e];
    float4 cf = *(const float4*)&g_coef[0];
    float l0 = as.x + ad.x + ea * cf.x;
    float l1 = as.y + ad.y + ea * cf.y;
    float l2 = as.z + ad.z + ea * cf.z;
    float l3 = as.w + ad.w + ea * cf.w;
    l0 = (l0 > 0.f) ? l0 : 0.2f * l0;
    l1 = (l1 > 0.f) ? l1 : 0.2f * l1;
    l2 = (l2 > 0.f) ? l2 : 0.2f * l2;
    l3 = (l3 > 0.f) ? l3 : 0.2f * l3;
    *(float4*)&g_logit[(size_t)e * 4] = make_float4(l0, l1, l2, l3);
    atomicMax(&g_m[d * 4 + 0], fkey(l0));
    atomicMax(&g_m[d * 4 + 1], fkey(l1));
    atomicMax(&g_m[d * 4 + 2], fkey(l2));
    atomicMax(&g_m[d * 4 + 3], fkey(l3));
}

__global__ void mdecode_kernel() {
    int i = blockIdx.x * blockDim.x + threadIdx.x;
    if (i >= NN * HEADS) return;
    unsigned k = g_m[i];
    ((float*)g_m)[i] = funkey(k);    // every node has a self-loop -> always a real key
}

// ex = exp(logit - m[dst]); den[dst] += ex  (vector RED)
__global__ void expsum_kernel() {
    int e = blockIdx.x * blockDim.x + threadIdx.x;
    if (e >= ETOT) return;
    int d = g_dst[e];
    float4 lg = *(const float4*)&g_logit[(size_t)e * 4];
    const float* mf = (const float*)g_m;
    float4 mv = *(const float4*)&mf[d * 4];
    float e0 = expf(lg.x - mv.x);
    float e1 = expf(lg.y - mv.y);
    float e2 = expf(lg.z - mv.z);
    float e3 = expf(lg.w - mv.w);
    *(float4*)&g_logit[(size_t)e * 4] = make_float4(e0, e1, e2, e3);
    asm volatile("red.global.add.v4.f32 [%0], {%1,%2,%3,%4};"
                 :: "l"(&g_den[d * 4]), "f"(e0), "f"(e1), "f"(e2), "f"(e3) : "memory");
}

// heavy pass: g[dst,:] += alpha * xh[src,:]   (one warp per edge, v4 RED)
__global__ __launch_bounds__(256) void aggregate_kernel() {
    int gw   = (blockIdx.x * blockDim.x + threadIdx.x) >> 5;
    int lane = threadIdx.x & 31;
    if (gw >= ETOT) return;
    int s = g_src[gw], d = g_dst[gw];
    float4 ex = *(const float4*)&g_logit[(size_t)gw * 4];
    float4 dn = *(const float4*)&g_den[d * 4];
    float a0 = ex.x / (dn.x + 1e-16f);
    float a1 = ex.y / (dn.y + 1e-16f);
    float a2 = ex.z / (dn.z + 1e-16f);
    float a3 = ex.w / (dn.w + 1e-16f);
    float al = (lane < 16) ? ((lane < 8) ? a0 : a1) : ((lane < 24) ? a2 : a3);
    int c = lane << 2;
    float4 xv = *(const float4*)&g_xh[(size_t)s * HID + c];
    asm volatile("red.global.add.v4.f32 [%0], {%1,%2,%3,%4};"
                 :: "l"(&g_gg[(size_t)d * HID + c]),
                    "f"(xv.x * al), "f"(xv.y * al), "f"(xv.z * al), "f"(xv.w * al)
                 : "memory");
}

// g += bg; accumulate global sum/sumsq (double) for graph layernorm
__global__ void ln_stats_kernel(const float* __restrict__ bg) {
    int i = blockIdx.x * blockDim.x + threadIdx.x;
    float v = 0.f;
    if (i < NN * HID) { v = g_gg[i] + bg[i & 127]; g_gg[i] = v; }
    double s = v, q = (double)v * v;
#pragma unroll
    for (int o = 16; o > 0; o >>= 1) {
        s += __shfl_down_sync(0xffffffffu, s, o);
        q += __shfl_down_sync(0xffffffffu, q, o);
    }
    __shared__ double ss[8], qq[8];
    int lane = threadIdx.x & 31, w = threadIdx.x >> 5;
    if (lane == 0) { ss[w] = s; qq[w] = q; }
    __syncthreads();
    if (threadIdx.x == 0) {
        double S = 0, Q = 0;
        for (int j = 0; j < 8; j++) { S += ss[j]; Q += qq[j]; }
        atomicAdd(&g_red[0], S);
        atomicAdd(&g_red[1], Q);
    }
}

// h = relu( (g - mean)*inv * ln_w + ln_b + h )
__global__ void update_h_kernel(const float* __restrict__ lnw, const float* __restrict__ lnb) {
    int i = blockIdx.x * blockDim.x + threadIdx.x;
    if (i >= NN * HID) return;
    const double cnt = (double)NN * (double)HID;
    float mean = (float)(g_red[0] / cnt);
    float var  = (float)(g_red[1] / cnt) - mean * mean;
    float inv  = rsqrtf(var + 1e-5f);
    int c = i & 127;
    float v = (g_gg[i] - mean) * inv * lnw[c] + lnb[c] + g_h[i];
    g_h[i] = v > 0.f ? v : 0.f;
}

// out = h @ Wout + bout   (warp per node)
__global__ void out_kernel(const float* __restrict__ Wout, const float* __restrict__ bout,
                           float* __restrict__ out) {
    int gw   = (blockIdx.x * blockDim.x + threadIdx.x) >> 5;
    int lane = threadIdx.x & 31;
    if (gw >= NN) return;
    float acc[OUT_DIM] = {0.f, 0.f, 0.f, 0.f, 0.f};
    for (int k = lane; k < HID; k += 32) {
        float hv = g_h[gw * HID + k];
#pragma unroll
        for (int o = 0; o < OUT_DIM; o++) acc[o] += hv * Wout[k * OUT_DIM + o];
    }
#pragma unroll
    for (int o = 0; o < OUT_DIM; o++)
#pragma unroll
        for (int sh = 16; sh > 0; sh >>= 1)
            acc[o] += __shfl_down_sync(0xffffffffu, acc[o], sh);
    if (lane == 0)
#pragma unroll
        for (int o = 0; o < OUT_DIM; o++) out[gw * OUT_DIM + o] = acc[o] + bout[o];
}

// ---------------- launch ----------------
static inline int dg(long long n, int b) { return (int)((n + b - 1) / b); }

extern "C" void kernel_launch(void* const* d_in, const int* in_sizes, int n_in,
                              void* d_out, int out_size) {
    const float* x      = (const float*)d_in[0];
    const int*   ei     = (const int*)d_in[1];
    const float* ea     = (const float*)d_in[2];
    const float* Win    = (const float*)d_in[3];
    const float* b_in   = (const float*)d_in[4];
    const float* Wg     = (const float*)d_in[5];
    const float* bg     = (const float*)d_in[6];
    const float* a_src  = (const float*)d_in[7];
    const float* a_dst  = (const float*)d_in[8];
    const float* We     = (const float*)d_in[9];
    const float* a_edge = (const float*)d_in[10];
    const float* ln_w   = (const float*)d_in[11];
    const float* ln_b   = (const float*)d_in[12];
    const float* Wout   = (const float*)d_in[13];
    const float* bout   = (const float*)d_in[14];
    float* out = (float*)d_out;

    detect_kernel<<<1, 256>>>(ei);
    setup_zero_kernel<<<dg(NN, 256), 256>>>();
    convert_kernel<<<dg(EE, 256), 256>>>(ei);
    deg_kernel<<<dg(EE, 256), 256>>>(ea);
    selfloop_kernel<<<dg(NN, 256), 256>>>();
    input_proj_kernel<<<NN, 128>>>(x, Win, b_in);

    for (int l = 0; l < LAYERS; l++) {
        layer_zero_kernel<<<dg((long long)NN * HID, 256), 256>>>();
        gemm128_kernel<<<dg(NN, 128), 256>>>(Wg + l * HID * HID);
        al_kernel<<<dg((long long)NN * 32, 256), 256>>>(a_src + l * HEADS * CH,
                                                        a_dst + l * HEADS * CH);
        coef_kernel<<<1, 32>>>(We + l * HID, a_edge + l * HEADS * CH);
        logits_kernel<<<dg(ETOT, 256), 256>>>();
        mdecode_kernel<<<dg(NN * HEADS, 256), 256>>>();
        expsum_kernel<<<dg(ETOT, 256), 256>>>();
        aggregate_kernel<<<dg((long long)ETOT * 32, 256), 256>>>();
        ln_stats_kernel<<<dg((long long)NN * HID, 256), 256>>>(bg + l * HID);
        update_h_kernel<<<dg((long long)NN * HID, 256), 256>>>(ln_w + l * HID, ln_b + l * HID);
    }
    out_kernel<<<dg((long long)NN * 32, 256), 256>>>(Wout, bout, out);
}